// round 12
// baseline (speedup 1.0000x reference)
#include <cuda_runtime.h>

// Local 5x5 variance, reflect padding. float32 [16,3,1024,1024] -> same.
//
// R10 structure (best measured: 3072 short CTAs, 2x128-row stages,
// double-buffered cp.async, 3 CTAs/SM) + incremental vertical sums:
// running 4-row partials S4/T4 per column make each output row cost
// 1 add + 1 sub per column per sum instead of a fresh 4-add 5-sum.

#define IMG 1024
#define NPLANES 48
#define TW 64
#define STAGE_H 128
#define STAGES 2            // 2 * 128 = 256 rows per CTA
#define SROWS 132           // STAGE_H + 4 halo
#define SC4 18              // 18 float4 = 72 floats per smem row
#define SBUF_ELEMS (SROWS * SC4)          // 2376 float4 per buffer
#define SMEM_BYTES (2 * SBUF_ELEMS * 16)  // 76032 bytes
#define THREADS 256

__device__ __forceinline__ int reflect_idx(int i, int n) {
    if (i < 0) i = -i;
    if (i >= n) i = 2 * (n - 1) - i;
    return i;
}

__device__ __forceinline__ void cp_async16(void* smem_dst, const void* gsrc) {
    unsigned sa = (unsigned)__cvta_generic_to_shared(smem_dst);
    asm volatile("cp.async.cg.shared.global [%0], [%1], 16;\n" :: "r"(sa), "l"(gsrc));
}

// Horizontal 5-sums of x and x^2 for 4 output columns (floats 2..9 of a|b|c).
__device__ __forceinline__ void rowsum(float4 a, float4 b, float4 c,
                                       float* __restrict__ hh,
                                       float* __restrict__ hh2) {
    float x0 = a.z, x1 = a.w, x2 = b.x, x3 = b.y;
    float x4 = b.z, x5 = b.w, x6 = c.x, x7 = c.y;

    float h0 = x0 + x1 + x2 + x3 + x4;
    hh[0] = h0;
    hh[1] = h0    - x0 + x5;
    hh[2] = hh[1] - x1 + x6;
    hh[3] = hh[2] - x2 + x7;

    float q0 = x0 * x0, q1 = x1 * x1, q2 = x2 * x2, q3 = x3 * x3;
    float q4 = x4 * x4, q5 = x5 * x5, q6 = x6 * x6, q7 = x7 * x7;
    float g0 = q0 + q1 + q2 + q3 + q4;
    hh2[0] = g0;
    hh2[1] = g0     - q0 + q5;
    hh2[2] = hh2[1] - q1 + q6;
    hh2[3] = hh2[2] - q2 + q7;
}

__global__ __launch_bounds__(THREADS, 3)
void locvar5_kernel(const float* __restrict__ in, float* __restrict__ out) {
    extern __shared__ float4 sbuf[];   // 2 buffers of SBUF_ELEMS

    const int plane = blockIdx.z;
    const float* __restrict__ src = in + (size_t)plane * IMG * IMG;
    float* __restrict__ dst = out + (size_t)plane * IMG * IMG;

    const int bx = blockIdx.x * TW;
    const int byBase = blockIdx.y * (STAGES * STAGE_H);
    const int tid = threadIdx.x;
    const bool colEdge = (bx == 0) || (bx + TW == IMG);

    const int tx4 = tid & 15;
    const int ty  = tid >> 4;          // 16 strips of 8 rows

    const int rowInit = tid / SC4;     // one div/mod total, reused per stage
    const int c4Init  = tid - rowInit * SC4;

    // ---- stage loader: async copies with incremental indexing ----
    auto load_stage = [&](int s, int buf) {
        float4* sb = sbuf + buf * SBUF_ELEMS;
        const int r0 = byBase + s * STAGE_H - 2;
        const bool rowsInterior = (r0 >= 0) && (r0 + SROWS <= IMG);
        int row = rowInit;
        int c4  = c4Init;
        while (row < SROWS) {
            const int gy = rowsInterior ? (r0 + row) : reflect_idx(r0 + row, IMG);
            const int gx = bx - 4 + c4 * 4;
            float4* sdst = sb + row * SC4 + c4;
            if (!colEdge || (c4 >= 1 && c4 <= 16)) {
                cp_async16(sdst, src + (size_t)gy * IMG + gx);
            } else {
                float4 v;
                v.x = src[(size_t)gy * IMG + reflect_idx(gx + 0, IMG)];
                v.y = src[(size_t)gy * IMG + reflect_idx(gx + 1, IMG)];
                v.z = src[(size_t)gy * IMG + reflect_idx(gx + 2, IMG)];
                v.w = src[(size_t)gy * IMG + reflect_idx(gx + 3, IMG)];
                *sdst = v;
            }
            // advance by 256 items: 256 = 14*18 + 4
            c4 += 4; row += 14;
            if (c4 >= SC4) { c4 -= SC4; ++row; }
        }
        asm volatile("cp.async.commit_group;\n" ::: "memory");
    };

    // ---- prologue: load stage 0, wait ----
    load_stage(0, 0);
    asm volatile("cp.async.wait_group 0;\n" ::: "memory");
    __syncthreads();

    const float inv_n = 1.0f / 25.0f;

    #pragma unroll
    for (int s = 0; s < STAGES; ++s) {
        if (s + 1 < STAGES) load_stage(s + 1, (s + 1) & 1);

        // ---- compute stage s: 8 output rows per thread ----
        const float4* sp = sbuf + (s & 1) * SBUF_ELEMS + (ty * 8) * SC4 + tx4;

        float h[5][4], h2[5][4];
        float S4[4], T4[4];
        #pragma unroll
        for (int j = 0; j < 4; ++j)
            rowsum(sp[j * SC4], sp[j * SC4 + 1], sp[j * SC4 + 2], h[j], h2[j]);
        #pragma unroll
        for (int cc = 0; cc < 4; ++cc) {
            S4[cc] = (h[0][cc] + h[1][cc]) + (h[2][cc] + h[3][cc]);
            T4[cc] = (h2[0][cc] + h2[1][cc]) + (h2[2][cc] + h2[3][cc]);
        }

        float4* op = (float4*)(dst + (size_t)(byBase + s * STAGE_H + ty * 8) * IMG
                                   + bx + tx4 * 4);
        #pragma unroll
        for (int j = 4; j < 12; ++j) {
            const int wnew = j % 5;        // slot receiving row j
            const int wold = (j + 1) % 5;  // slot holding row j-4 (next oldest)
            rowsum(sp[j * SC4], sp[j * SC4 + 1], sp[j * SC4 + 2],
                   h[wnew], h2[wnew]);
            float4 o;
            float* po = (float*)&o;
            #pragma unroll
            for (int cc = 0; cc < 4; ++cc) {
                const float S = S4[cc] + h[wnew][cc];
                const float T = T4[cc] + h2[wnew][cc];
                const float m = S * inv_n;
                po[cc] = fmaf(-m, m, T * inv_n);
                S4[cc] = S - h[wold][cc];
                T4[cc] = T - h2[wold][cc];
            }
            *op = o;
            op += IMG / 4;
        }

        if (s + 1 < STAGES) {
            asm volatile("cp.async.wait_group 0;\n" ::: "memory");
            __syncthreads();
        }
    }
}

extern "C" void kernel_launch(void* const* d_in, const int* in_sizes, int n_in,
                              void* d_out, int out_size) {
    const float* in = (const float*)d_in[0];
    float* out = (float*)d_out;
    cudaFuncSetAttribute(locvar5_kernel,
                         cudaFuncAttributeMaxDynamicSharedMemorySize, SMEM_BYTES);
    dim3 grid(IMG / TW, IMG / (STAGES * STAGE_H), NPLANES);
    locvar5_kernel<<<grid, THREADS, SMEM_BYTES>>>(in, out);
}

// round 13
// speedup vs baseline: 1.2096x; 1.2096x over previous
#include <cuda_runtime.h>

// Local 5x5 variance, reflect padding. float32 [16,3,1024,1024] -> same.
//
// R10 compute core (12 rowsums / 8 output rows per thread, full 5-row sums,
// no serial chains) reconfigured for higher occupancy:
//   128-thread CTAs, 64-row stages -> 39.1KB smem/CTA and 10.2K regs/CTA
//   => 5 CTAs/SM (40 warps/SM vs R10's 24). STAGES=4 (256 rows per CTA),
//   grid = 3072 CTAs = 4.15 waves of 740. Double-buffered cp.async pipeline.

#define IMG 1024
#define NPLANES 48
#define TW 64
#define STAGE_H 64
#define STAGES 4            // 4 * 64 = 256 rows per CTA
#define SROWS 68            // STAGE_H + 4 halo
#define SC4 18              // 18 float4 = 72 floats per smem row
#define SBUF_ELEMS (SROWS * SC4)          // 1224 float4 per buffer
#define SMEM_BYTES (2 * SBUF_ELEMS * 16)  // 39168 bytes
#define THREADS 128

__device__ __forceinline__ int reflect_idx(int i, int n) {
    if (i < 0) i = -i;
    if (i >= n) i = 2 * (n - 1) - i;
    return i;
}

__device__ __forceinline__ void cp_async16(void* smem_dst, const void* gsrc) {
    unsigned sa = (unsigned)__cvta_generic_to_shared(smem_dst);
    asm volatile("cp.async.cg.shared.global [%0], [%1], 16;\n" :: "r"(sa), "l"(gsrc));
}

// Horizontal 5-sums of x and x^2 for 4 output columns (floats 2..9 of a|b|c).
__device__ __forceinline__ void rowsum(float4 a, float4 b, float4 c,
                                       float* __restrict__ hh,
                                       float* __restrict__ hh2) {
    float x0 = a.z, x1 = a.w, x2 = b.x, x3 = b.y;
    float x4 = b.z, x5 = b.w, x6 = c.x, x7 = c.y;

    float h0 = x0 + x1 + x2 + x3 + x4;
    hh[0] = h0;
    hh[1] = h0    - x0 + x5;
    hh[2] = hh[1] - x1 + x6;
    hh[3] = hh[2] - x2 + x7;

    float q0 = x0 * x0, q1 = x1 * x1, q2 = x2 * x2, q3 = x3 * x3;
    float q4 = x4 * x4, q5 = x5 * x5, q6 = x6 * x6, q7 = x7 * x7;
    float g0 = q0 + q1 + q2 + q3 + q4;
    hh2[0] = g0;
    hh2[1] = g0     - q0 + q5;
    hh2[2] = hh2[1] - q1 + q6;
    hh2[3] = hh2[2] - q2 + q7;
}

__global__ __launch_bounds__(THREADS, 5)
void locvar5_kernel(const float* __restrict__ in, float* __restrict__ out) {
    extern __shared__ float4 sbuf[];   // 2 buffers of SBUF_ELEMS

    const int plane = blockIdx.z;
    const float* __restrict__ src = in + (size_t)plane * IMG * IMG;
    float* __restrict__ dst = out + (size_t)plane * IMG * IMG;

    const int bx = blockIdx.x * TW;
    const int byBase = blockIdx.y * (STAGES * STAGE_H);
    const int tid = threadIdx.x;
    const bool colEdge = (bx == 0) || (bx + TW == IMG);

    const int tx4 = tid & 15;
    const int ty  = tid >> 4;          // 8 strips of 8 rows

    const int rowInit = tid / SC4;     // one div/mod total, reused per stage
    const int c4Init  = tid - rowInit * SC4;

    // ---- stage loader: async copies with incremental indexing ----
    auto load_stage = [&](int s, int buf) {
        float4* sb = sbuf + buf * SBUF_ELEMS;
        const int r0 = byBase + s * STAGE_H - 2;
        const bool rowsInterior = (r0 >= 0) && (r0 + SROWS <= IMG);
        int row = rowInit;
        int c4  = c4Init;
        while (row < SROWS) {
            const int gy = rowsInterior ? (r0 + row) : reflect_idx(r0 + row, IMG);
            const int gx = bx - 4 + c4 * 4;
            float4* sdst = sb + row * SC4 + c4;
            if (!colEdge || (c4 >= 1 && c4 <= 16)) {
                cp_async16(sdst, src + (size_t)gy * IMG + gx);
            } else {
                float4 v;
                v.x = src[(size_t)gy * IMG + reflect_idx(gx + 0, IMG)];
                v.y = src[(size_t)gy * IMG + reflect_idx(gx + 1, IMG)];
                v.z = src[(size_t)gy * IMG + reflect_idx(gx + 2, IMG)];
                v.w = src[(size_t)gy * IMG + reflect_idx(gx + 3, IMG)];
                *sdst = v;
            }
            // advance by 128 items: 128 = 7*18 + 2
            c4 += 2; row += 7;
            if (c4 >= SC4) { c4 -= SC4; ++row; }
        }
        asm volatile("cp.async.commit_group;\n" ::: "memory");
    };

    // ---- prologue: load stage 0, wait ----
    load_stage(0, 0);
    asm volatile("cp.async.wait_group 0;\n" ::: "memory");
    __syncthreads();

    const float inv_n = 1.0f / 25.0f;

    #pragma unroll
    for (int s = 0; s < STAGES; ++s) {
        if (s + 1 < STAGES) load_stage(s + 1, (s + 1) & 1);

        // ---- compute stage s: 8 output rows per thread ----
        const float4* sp = sbuf + (s & 1) * SBUF_ELEMS + (ty * 8) * SC4 + tx4;

        float h[5][4], h2[5][4];
        #pragma unroll
        for (int j = 0; j < 4; ++j)
            rowsum(sp[j * SC4], sp[j * SC4 + 1], sp[j * SC4 + 2], h[j], h2[j]);

        float4* op = (float4*)(dst + (size_t)(byBase + s * STAGE_H + ty * 8) * IMG
                                   + bx + tx4 * 4);
        #pragma unroll
        for (int j = 4; j < 12; ++j) {
            rowsum(sp[j * SC4], sp[j * SC4 + 1], sp[j * SC4 + 2],
                   h[j % 5], h2[j % 5]);
            float4 o;
            float* po = (float*)&o;
            #pragma unroll
            for (int cc = 0; cc < 4; ++cc) {
                const float S = h[0][cc] + h[1][cc] + h[2][cc] + h[3][cc] + h[4][cc];
                const float T = h2[0][cc] + h2[1][cc] + h2[2][cc] + h2[3][cc] + h2[4][cc];
                const float m = S * inv_n;
                po[cc] = fmaf(-m, m, T * inv_n);
            }
            *op = o;
            op += IMG / 4;
        }

        if (s + 1 < STAGES) {
            asm volatile("cp.async.wait_group 0;\n" ::: "memory");
            __syncthreads();
        }
    }
}

extern "C" void kernel_launch(void* const* d_in, const int* in_sizes, int n_in,
                              void* d_out, int out_size) {
    const float* in = (const float*)d_in[0];
    float* out = (float*)d_out;
    cudaFuncSetAttribute(locvar5_kernel,
                         cudaFuncAttributeMaxDynamicSharedMemorySize, SMEM_BYTES);
    dim3 grid(IMG / TW, IMG / (STAGES * STAGE_H), NPLANES);
    locvar5_kernel<<<grid, THREADS, SMEM_BYTES>>>(in, out);
}

// round 14
// speedup vs baseline: 1.3816x; 1.1423x over previous
#include <cuda_runtime.h>

// Local 5x5 variance, reflect padding. float32 [16,3,1024,1024] -> same.
//
// R10 structure (best measured: 3072 CTAs, 2x128-row stages, double-buffered
// cp.async, 256 thr, 3 CTAs/SM) with packed f32x2 arithmetic (sm_103a FFMA2
// path, PTX-only): horizontal window sums, vertical 5-sums and the variance
// epilogue all operate on column pairs -> ~25-30% fewer FP instructions,
// identical data flow (no serial chains, same ring register footprint).

#define IMG 1024
#define NPLANES 48
#define TW 64
#define STAGE_H 128
#define STAGES 2            // 2 * 128 = 256 rows per CTA
#define SROWS 132           // STAGE_H + 4 halo
#define SC4 18              // 18 float4 = 72 floats per smem row
#define SBUF_ELEMS (SROWS * SC4)          // 2376 float4 per buffer
#define SMEM_BYTES (2 * SBUF_ELEMS * 16)  // 76032 bytes
#define THREADS 256

typedef unsigned long long u64;

__device__ __forceinline__ u64 pk2(float lo, float hi) {
    u64 r; asm("mov.b64 %0, {%1, %2};" : "=l"(r) : "f"(lo), "f"(hi)); return r;
}
__device__ __forceinline__ u64 addx2(u64 a, u64 b) {
    u64 r; asm("add.rn.f32x2 %0, %1, %2;" : "=l"(r) : "l"(a), "l"(b)); return r;
}
__device__ __forceinline__ u64 mulx2(u64 a, u64 b) {
    u64 r; asm("mul.rn.f32x2 %0, %1, %2;" : "=l"(r) : "l"(a), "l"(b)); return r;
}
__device__ __forceinline__ u64 fmax2(u64 a, u64 b, u64 c) {
    u64 r; asm("fma.rn.f32x2 %0, %1, %2, %3;" : "=l"(r) : "l"(a), "l"(b), "l"(c)); return r;
}
__device__ __forceinline__ void upk2(u64 v, float& lo, float& hi) {
    asm("mov.b64 {%0, %1}, %2;" : "=f"(lo), "=f"(hi) : "l"(v));
}

__device__ __forceinline__ int reflect_idx(int i, int n) {
    if (i < 0) i = -i;
    if (i >= n) i = 2 * (n - 1) - i;
    return i;
}

__device__ __forceinline__ void cp_async16(void* smem_dst, const void* gsrc) {
    unsigned sa = (unsigned)__cvta_generic_to_shared(smem_dst);
    asm volatile("cp.async.cg.shared.global [%0], [%1], 16;\n" :: "r"(sa), "l"(gsrc));
}

// Packed horizontal 5-sums of x and x^2 for 4 output columns.
// Window floats 2..9 of (a|b|c); column pairs (0,1) and (2,3).
__device__ __forceinline__ void rowsum_pk(float4 a, float4 b, float4 c,
                                          u64& s01, u64& s23,
                                          u64& t01, u64& t23) {
    const float x0 = a.z, x1 = a.w, x2 = b.x, x3 = b.y;
    const float x4 = b.z, x5 = b.w, x6 = c.x, x7 = c.y;

    const u64 P0 = pk2(x0, x1), P1 = pk2(x1, x2), P2 = pk2(x2, x3);
    const u64 P3 = pk2(x3, x4), P4 = pk2(x4, x5), P5 = pk2(x5, x6);
    const u64 P6 = pk2(x6, x7);

    const u64 p01 = addx2(P0, P1);
    const u64 p23 = addx2(P2, P3);
    const u64 p45 = addx2(P4, P5);
    s01 = addx2(p01, addx2(p23, P4));
    s23 = addx2(p23, addx2(p45, P6));

    const u64 Q0 = mulx2(P0, P0), Q1 = mulx2(P1, P1), Q2 = mulx2(P2, P2);
    const u64 Q3 = mulx2(P3, P3), Q4 = mulx2(P4, P4), Q5 = mulx2(P5, P5);
    const u64 Q6 = mulx2(P6, P6);

    const u64 q01 = addx2(Q0, Q1);
    const u64 q23 = addx2(Q2, Q3);
    const u64 q45 = addx2(Q4, Q5);
    t01 = addx2(q01, addx2(q23, Q4));
    t23 = addx2(q23, addx2(q45, Q6));
}

__global__ __launch_bounds__(THREADS, 3)
void locvar5_kernel(const float* __restrict__ in, float* __restrict__ out) {
    extern __shared__ float4 sbuf[];   // 2 buffers of SBUF_ELEMS

    const int plane = blockIdx.z;
    const float* __restrict__ src = in + (size_t)plane * IMG * IMG;
    float* __restrict__ dst = out + (size_t)plane * IMG * IMG;

    const int bx = blockIdx.x * TW;
    const int byBase = blockIdx.y * (STAGES * STAGE_H);
    const int tid = threadIdx.x;
    const bool colEdge = (bx == 0) || (bx + TW == IMG);

    const int tx4 = tid & 15;
    const int ty  = tid >> 4;          // 16 strips of 8 rows

    const int rowInit = tid / SC4;     // one div/mod total, reused per stage
    const int c4Init  = tid - rowInit * SC4;

    // ---- stage loader: async copies with incremental indexing ----
    auto load_stage = [&](int s, int buf) {
        float4* sb = sbuf + buf * SBUF_ELEMS;
        const int r0 = byBase + s * STAGE_H - 2;
        const bool rowsInterior = (r0 >= 0) && (r0 + SROWS <= IMG);
        int row = rowInit;
        int c4  = c4Init;
        while (row < SROWS) {
            const int gy = rowsInterior ? (r0 + row) : reflect_idx(r0 + row, IMG);
            const int gx = bx - 4 + c4 * 4;
            float4* sdst = sb + row * SC4 + c4;
            if (!colEdge || (c4 >= 1 && c4 <= 16)) {
                cp_async16(sdst, src + (size_t)gy * IMG + gx);
            } else {
                float4 v;
                v.x = src[(size_t)gy * IMG + reflect_idx(gx + 0, IMG)];
                v.y = src[(size_t)gy * IMG + reflect_idx(gx + 1, IMG)];
                v.z = src[(size_t)gy * IMG + reflect_idx(gx + 2, IMG)];
                v.w = src[(size_t)gy * IMG + reflect_idx(gx + 3, IMG)];
                *sdst = v;
            }
            // advance by 256 items: 256 = 14*18 + 4
            c4 += 4; row += 14;
            if (c4 >= SC4) { c4 -= SC4; ++row; }
        }
        asm volatile("cp.async.commit_group;\n" ::: "memory");
    };

    // ---- prologue: load stage 0, wait ----
    load_stage(0, 0);
    asm volatile("cp.async.wait_group 0;\n" ::: "memory");
    __syncthreads();

    const float inv_n = 1.0f / 25.0f;
    const u64 INV  = pk2(inv_n, inv_n);
    const u64 NINV = pk2(-inv_n, -inv_n);

    #pragma unroll
    for (int s = 0; s < STAGES; ++s) {
        if (s + 1 < STAGES) load_stage(s + 1, (s + 1) & 1);

        // ---- compute stage s: 8 output rows per thread ----
        const float4* sp = sbuf + (s & 1) * SBUF_ELEMS + (ty * 8) * SC4 + tx4;

        u64 hs01[5], hs23[5], ht01[5], ht23[5];
        #pragma unroll
        for (int j = 0; j < 4; ++j)
            rowsum_pk(sp[j * SC4], sp[j * SC4 + 1], sp[j * SC4 + 2],
                      hs01[j], hs23[j], ht01[j], ht23[j]);

        float4* op = (float4*)(dst + (size_t)(byBase + s * STAGE_H + ty * 8) * IMG
                                   + bx + tx4 * 4);
        #pragma unroll
        for (int j = 4; j < 12; ++j) {
            const int w = j % 5;
            rowsum_pk(sp[j * SC4], sp[j * SC4 + 1], sp[j * SC4 + 2],
                      hs01[w], hs23[w], ht01[w], ht23[w]);

            const u64 S01 = addx2(addx2(hs01[0], hs01[1]),
                                  addx2(hs01[2], addx2(hs01[3], hs01[4])));
            const u64 S23 = addx2(addx2(hs23[0], hs23[1]),
                                  addx2(hs23[2], addx2(hs23[3], hs23[4])));
            const u64 T01 = addx2(addx2(ht01[0], ht01[1]),
                                  addx2(ht01[2], addx2(ht01[3], ht01[4])));
            const u64 T23 = addx2(addx2(ht23[0], ht23[1]),
                                  addx2(ht23[2], addx2(ht23[3], ht23[4])));

            // var = T/25 - (S/25)^2  ==  (S*inv) * (S*-inv) + T*inv
            const u64 v01 = fmax2(mulx2(S01, INV), mulx2(S01, NINV), mulx2(T01, INV));
            const u64 v23 = fmax2(mulx2(S23, INV), mulx2(S23, NINV), mulx2(T23, INV));

            float4 o;
            upk2(v01, o.x, o.y);
            upk2(v23, o.z, o.w);
            *op = o;
            op += IMG / 4;
        }

        if (s + 1 < STAGES) {
            asm volatile("cp.async.wait_group 0;\n" ::: "memory");
            __syncthreads();
        }
    }
}

extern "C" void kernel_launch(void* const* d_in, const int* in_sizes, int n_in,
                              void* d_out, int out_size) {
    const float* in = (const float*)d_in[0];
    float* out = (float*)d_out;
    cudaFuncSetAttribute(locvar5_kernel,
                         cudaFuncAttributeMaxDynamicSharedMemorySize, SMEM_BYTES);
    dim3 grid(IMG / TW, IMG / (STAGES * STAGE_H), NPLANES);
    locvar5_kernel<<<grid, THREADS, SMEM_BYTES>>>(in, out);
}